// round 3
// baseline (speedup 1.0000x reference)
#include <cuda_runtime.h>
#include <cuda_bf16.h>
#include <cstdint>

// Problem shapes (fixed by the dataset): N=16384, C=2048, D=512
#define MAXN 16384
#define MAXC 2048

#define MARGIN 1.0f
#define NORM_EPS 1e-12f

// ---------------- scratch (no allocations allowed) ----------------
__device__ float    d_inv[MAXN];        // 1 / max(||WO_n||, eps)
__device__ float    d_x2[MAXN];         // sum(WO_n_normalized^2)  (~1.0)
__device__ float    d_e2[MAXC];         // ||emb_c||^2
__device__ float    d_labelDist[MAXN];  // dist to true class
__device__ unsigned d_minBits[MAXN];    // min dist over other classes, as float bits

// ---------------- kernel A: WO row stats + init ----------------
// one warp per row, 8 warps per block
__global__ void wo_row_stats(const float* __restrict__ WO, int N, int D) {
    int warp = blockIdx.x * 8 + (threadIdx.x >> 5);
    int lane = threadIdx.x & 31;
    if (warp >= N) return;
    const float4* row = reinterpret_cast<const float4*>(WO + (size_t)warp * D);
    int nv = D >> 2;
    float s = 0.f;
    for (int i = lane; i < nv; i += 32) {
        float4 v = row[i];
        s += v.x * v.x + v.y * v.y + v.z * v.z + v.w * v.w;
    }
    #pragma unroll
    for (int off = 16; off > 0; off >>= 1)
        s += __shfl_xor_sync(0xffffffffu, s, off);
    if (lane == 0) {
        float norm = sqrtf(s);
        float inv = 1.f / fmaxf(norm, NORM_EPS);
        d_inv[warp] = inv;
        d_x2[warp]  = s * inv * inv;
        d_minBits[warp] = 0x7F800000u;  // +inf
    }
}

// ---------------- kernel B: emb row norms^2 ----------------
__global__ void emb_row_stats(const float* __restrict__ E, int C, int D) {
    int warp = blockIdx.x * 8 + (threadIdx.x >> 5);
    int lane = threadIdx.x & 31;
    if (warp >= C) return;
    const float4* row = reinterpret_cast<const float4*>(E + (size_t)warp * D);
    int nv = D >> 2;
    float s = 0.f;
    for (int i = lane; i < nv; i += 32) {
        float4 v = row[i];
        s += v.x * v.x + v.y * v.y + v.z * v.z + v.w * v.w;
    }
    #pragma unroll
    for (int off = 16; off > 0; off >>= 1)
        s += __shfl_xor_sync(0xffffffffu, s, off);
    if (lane == 0) d_e2[warp] = s;
}

// ---------------- kernel C: fused SGEMM + dist + min/label epilogue ----------------
// Tile: BM=128 rows x BN=128 cols, BK=16, 256 threads, 8x8 per-thread microtile.
// grid.x = C-splits (each block loops over ctilesPerBlock BN-tiles)
// grid.y = N / BM row blocks
#define BM 128
#define BN 128
#define BK 16
#define SPAD 4

__global__ __launch_bounds__(256, 2)
void fused_dist_gemm(const float* __restrict__ WO,
                     const float* __restrict__ E,
                     const int* __restrict__ label,
                     int N, int C, int D, int ctilesPerBlock) {
    __shared__ float As[2][BK][BM + SPAD];
    __shared__ float Bs[2][BK][BN + SPAD];
    __shared__ unsigned rowMin[BM];
    __shared__ int   rowLabel[BM];
    __shared__ float rowInv[BM];
    __shared__ float rowX2[BM];

    const int tid = threadIdx.x;
    const int rowBase  = blockIdx.y * BM;
    const int colStart = blockIdx.x * (ctilesPerBlock * BN);

    if (tid < BM) {
        int r = rowBase + tid;
        rowMin[tid]   = 0x7F800000u;
        rowLabel[tid] = label[r];
        rowInv[tid]   = d_inv[r];
        rowX2[tid]    = d_x2[r];
    }

    const int tx = tid & 15;        // col group 0..15
    const int ty = tid >> 4;        // row group 0..15
    // loader mapping: 4 threads per row (16 floats = 4 float4), 64 rows/pass, 2 passes
    const int aRow = tid >> 2;          // 0..63
    const int aCol = (tid & 3) << 2;    // 0,4,8,12

    const int nKT = D / BK;

    for (int ct = 0; ct < ctilesPerBlock; ++ct) {
        const int colBase = colStart + ct * BN;

        float acc[8][8];
        #pragma unroll
        for (int i = 0; i < 8; ++i)
            #pragma unroll
            for (int j = 0; j < 8; ++j) acc[i][j] = 0.f;

        const float* Agb = WO + (size_t)(rowBase + aRow) * D + aCol;
        const float* Bgb = E  + (size_t)(colBase + aRow) * D + aCol;

        __syncthreads();   // smem tiles & rowLabel etc. ready / reusable

        // prologue: load k-tile 0 into buffer 0
        float4 a0r = *reinterpret_cast<const float4*>(Agb);
        float4 a1r = *reinterpret_cast<const float4*>(Agb + (size_t)64 * D);
        float4 b0r = *reinterpret_cast<const float4*>(Bgb);
        float4 b1r = *reinterpret_cast<const float4*>(Bgb + (size_t)64 * D);
        {
            As[0][aCol + 0][aRow] = a0r.x; As[0][aCol + 1][aRow] = a0r.y;
            As[0][aCol + 2][aRow] = a0r.z; As[0][aCol + 3][aRow] = a0r.w;
            As[0][aCol + 0][aRow + 64] = a1r.x; As[0][aCol + 1][aRow + 64] = a1r.y;
            As[0][aCol + 2][aRow + 64] = a1r.z; As[0][aCol + 3][aRow + 64] = a1r.w;
            Bs[0][aCol + 0][aRow] = b0r.x; Bs[0][aCol + 1][aRow] = b0r.y;
            Bs[0][aCol + 2][aRow] = b0r.z; Bs[0][aCol + 3][aRow] = b0r.w;
            Bs[0][aCol + 0][aRow + 64] = b1r.x; Bs[0][aCol + 1][aRow + 64] = b1r.y;
            Bs[0][aCol + 2][aRow + 64] = b1r.z; Bs[0][aCol + 3][aRow + 64] = b1r.w;
        }
        __syncthreads();

        int buf = 0;
        for (int kt = 0; kt < nKT; ++kt) {
            // prefetch next k-tile (global -> regs) while computing
            if (kt + 1 < nKT) {
                const float* Ag = Agb + (kt + 1) * BK;
                const float* Bg = Bgb + (kt + 1) * BK;
                a0r = *reinterpret_cast<const float4*>(Ag);
                a1r = *reinterpret_cast<const float4*>(Ag + (size_t)64 * D);
                b0r = *reinterpret_cast<const float4*>(Bg);
                b1r = *reinterpret_cast<const float4*>(Bg + (size_t)64 * D);
            }

            #pragma unroll
            for (int kk = 0; kk < BK; ++kk) {
                float4 af0 = *reinterpret_cast<const float4*>(&As[buf][kk][ty * 4]);
                float4 af1 = *reinterpret_cast<const float4*>(&As[buf][kk][ty * 4 + 64]);
                float4 bf0 = *reinterpret_cast<const float4*>(&Bs[buf][kk][tx * 4]);
                float4 bf1 = *reinterpret_cast<const float4*>(&Bs[buf][kk][tx * 4 + 64]);
                float a[8] = {af0.x, af0.y, af0.z, af0.w, af1.x, af1.y, af1.z, af1.w};
                float b[8] = {bf0.x, bf0.y, bf0.z, bf0.w, bf1.x, bf1.y, bf1.z, bf1.w};
                #pragma unroll
                for (int i = 0; i < 8; ++i)
                    #pragma unroll
                    for (int j = 0; j < 8; ++j)
                        acc[i][j] = fmaf(a[i], b[j], acc[i][j]);
            }

            if (kt + 1 < nKT) {
                int nb = buf ^ 1;
                // safe: readers of nb finished before the sync at end of iter kt-1
                As[nb][aCol + 0][aRow] = a0r.x; As[nb][aCol + 1][aRow] = a0r.y;
                As[nb][aCol + 2][aRow] = a0r.z; As[nb][aCol + 3][aRow] = a0r.w;
                As[nb][aCol + 0][aRow + 64] = a1r.x; As[nb][aCol + 1][aRow + 64] = a1r.y;
                As[nb][aCol + 2][aRow + 64] = a1r.z; As[nb][aCol + 3][aRow + 64] = a1r.w;
                Bs[nb][aCol + 0][aRow] = b0r.x; Bs[nb][aCol + 1][aRow] = b0r.y;
                Bs[nb][aCol + 2][aRow] = b0r.z; Bs[nb][aCol + 3][aRow] = b0r.w;
                Bs[nb][aCol + 0][aRow + 64] = b1r.x; Bs[nb][aCol + 1][aRow + 64] = b1r.y;
                Bs[nb][aCol + 2][aRow + 64] = b1r.z; Bs[nb][aCol + 3][aRow + 64] = b1r.w;
                __syncthreads();
                buf = nb;
            }
        }

        // epilogue: dist = sqrt(max(x2 + e2 - 2*dot*inv, 0)); label capture + min
        #pragma unroll
        for (int i = 0; i < 8; ++i) {
            int rl = ty * 4 + ((i < 4) ? i : (64 + i - 4));
            int r = rowBase + rl;
            float invn = rowInv[rl];
            float x2v  = rowX2[rl];
            int   lab  = rowLabel[rl];
            float m = __int_as_float(0x7F800000);
            #pragma unroll
            for (int j = 0; j < 8; ++j) {
                int cl = tx * 4 + ((j < 4) ? j : (64 + j - 4));
                int c = colBase + cl;
                float d2 = x2v + __ldg(&d_e2[c]) - 2.f * acc[i][j] * invn;
                float dist = sqrtf(fmaxf(d2, 0.f));
                if (c == lab) d_labelDist[r] = dist;
                else          m = fminf(m, dist);
            }
            atomicMin(&rowMin[rl], __float_as_uint(m));
        }
    }

    __syncthreads();
    if (tid < BM)
        atomicMin(&d_minBits[rowBase + tid], rowMin[tid]);
}

// ---------------- kernel D: deterministic mean ----------------
__global__ void finalize_mean(float* __restrict__ out, int N) {
    __shared__ float sbuf[1024];
    int tid = threadIdx.x;
    float s = 0.f;
    for (int n = tid; n < N; n += 1024)
        s += MARGIN + d_labelDist[n] - __uint_as_float(d_minBits[n]);
    sbuf[tid] = s;
    __syncthreads();
    for (int off = 512; off > 0; off >>= 1) {
        if (tid < off) sbuf[tid] += sbuf[tid + off];
        __syncthreads();
    }
    if (tid == 0) out[0] = sbuf[0] / (float)N;
}

// ---------------- launch ----------------
extern "C" void kernel_launch(void* const* d_in, const int* in_sizes, int n_in,
                              void* d_out, int out_size) {
    const float* WO    = (const float*)d_in[0];
    const float* E     = (const float*)d_in[1];
    const int*   label = (const int*)d_in[2];   // int32 (JAX x64 disabled downcasts int64)
    float* out = (float*)d_out;

    int N = in_sizes[2];             // 16384
    int D = in_sizes[0] / N;         // 512
    int C = in_sizes[1] / D;         // 2048

    wo_row_stats<<<(N + 7) / 8, 256>>>(WO, N, D);
    emb_row_stats<<<(C + 7) / 8, 256>>>(E, C, D);

    const int cSplits = 2;
    int ctilesPerBlock = C / (cSplits * BN);   // 8
    dim3 grid(cSplits, N / BM);                // (2, 128)
    fused_dist_gemm<<<grid, 256>>>(WO, E, label, N, C, D, ctilesPerBlock);

    finalize_mean<<<1, 1024>>>(out, N);
}

// round 7
// speedup vs baseline: 7.5380x; 7.5380x over previous
#include <cuda_runtime.h>
#include <cuda_bf16.h>
#include <cstdint>

// Fixed shapes: N=16384 rows, C=2048 classes, D=512
#define N_ROWS 16384
#define N_CLS  2048
#define DIM    512
#define MARGIN 1.0f

// ---------------- device scratch (no runtime allocation) ----------------
__device__ __nv_bfloat16 g_WO_bf[N_ROWS * DIM];  // normalized WO, bf16
__device__ __nv_bfloat16 g_E_bf [N_CLS * DIM];   // emb, bf16
__device__ float    d_x2[N_ROWS];                // ||normalized row||^2 (fp32)
__device__ float    d_e2[N_CLS];                 // ||emb_c||^2 (fp32)
__device__ float    d_labelD2[N_ROWS];           // d^2 to true class
__device__ unsigned d_minBits[N_ROWS];           // min d^2 over other classes (float bits)

// ---------------- helpers ----------------
__device__ __forceinline__ uint32_t smem_to_u32(const void* p) {
    uint32_t a;
    asm("{ .reg .u64 t; cvta.to.shared.u64 t, %1; cvt.u32.u64 %0, t; }" : "=r"(a) : "l"(p));
    return a;
}
#define CP_ASYNC_16(dst_u32, src_ptr) \
    asm volatile("cp.async.cg.shared.global [%0], [%1], 16;" :: "r"(dst_u32), "l"(src_ptr))
#define CP_ASYNC_COMMIT() asm volatile("cp.async.commit_group;" ::: "memory")
#define CP_ASYNC_WAIT1()  asm volatile("cp.async.wait_group 1;" ::: "memory")
#define CP_ASYNC_WAIT0()  asm volatile("cp.async.wait_group 0;" ::: "memory")
#define SW128(off) ((off) ^ (((off) >> 3) & 0x70))

__device__ __forceinline__ void ldsm_x4(uint32_t* r, uint32_t addr) {
    asm volatile("ldmatrix.sync.aligned.m8n8.x4.shared.b16 {%0,%1,%2,%3}, [%4];"
        : "=r"(r[0]), "=r"(r[1]), "=r"(r[2]), "=r"(r[3]) : "r"(addr));
}
__device__ __forceinline__ void mma_16816(float* c, const uint32_t* a, const uint32_t* b) {
    asm volatile(
        "mma.sync.aligned.m16n8k16.row.col.f32.bf16.bf16.f32 "
        "{%0,%1,%2,%3}, {%4,%5,%6,%7}, {%8,%9}, {%0,%1,%2,%3};"
        : "+f"(c[0]), "+f"(c[1]), "+f"(c[2]), "+f"(c[3])
        : "r"(a[0]), "r"(a[1]), "r"(a[2]), "r"(a[3]), "r"(b[0]), "r"(b[1]));
}

// ---------------- kernel 1: normalize WO -> bf16, x2, init minBits ----------------
__global__ void prep_wo(const float* __restrict__ WO) {
    int row = blockIdx.x * 8 + (threadIdx.x >> 5);
    int lane = threadIdx.x & 31;
    const float4* src = reinterpret_cast<const float4*>(WO + (size_t)row * DIM);
    float4 v[4];
    float s = 0.f;
    #pragma unroll
    for (int c = 0; c < 4; ++c) {
        v[c] = src[lane + 32 * c];
        s += v[c].x * v[c].x + v[c].y * v[c].y + v[c].z * v[c].z + v[c].w * v[c].w;
    }
    #pragma unroll
    for (int off = 16; off > 0; off >>= 1) s += __shfl_xor_sync(0xffffffffu, s, off);
    float inv = 1.f / fmaxf(sqrtf(s), 1e-12f);
    if (lane == 0) {
        d_x2[row] = (s * inv) * inv;
        d_minBits[row] = 0x7F800000u;  // +inf
    }
    uint2* dst = reinterpret_cast<uint2*>(g_WO_bf + (size_t)row * DIM);
    #pragma unroll
    for (int c = 0; c < 4; ++c) {
        __nv_bfloat162 p0 = __float22bfloat162_rn(make_float2(v[c].x * inv, v[c].y * inv));
        __nv_bfloat162 p1 = __float22bfloat162_rn(make_float2(v[c].z * inv, v[c].w * inv));
        uint2 u;
        u.x = *reinterpret_cast<uint32_t*>(&p0);
        u.y = *reinterpret_cast<uint32_t*>(&p1);
        dst[lane + 32 * c] = u;
    }
}

// ---------------- kernel 2: emb -> bf16, e2 ----------------
__global__ void prep_e(const float* __restrict__ E) {
    int row = blockIdx.x * 8 + (threadIdx.x >> 5);
    int lane = threadIdx.x & 31;
    const float4* src = reinterpret_cast<const float4*>(E + (size_t)row * DIM);
    float4 v[4];
    float s = 0.f;
    #pragma unroll
    for (int c = 0; c < 4; ++c) {
        v[c] = src[lane + 32 * c];
        s += v[c].x * v[c].x + v[c].y * v[c].y + v[c].z * v[c].z + v[c].w * v[c].w;
    }
    #pragma unroll
    for (int off = 16; off > 0; off >>= 1) s += __shfl_xor_sync(0xffffffffu, s, off);
    if (lane == 0) d_e2[row] = s;
    uint2* dst = reinterpret_cast<uint2*>(g_E_bf + (size_t)row * DIM);
    #pragma unroll
    for (int c = 0; c < 4; ++c) {
        __nv_bfloat162 p0 = __float22bfloat162_rn(make_float2(v[c].x, v[c].y));
        __nv_bfloat162 p1 = __float22bfloat162_rn(make_float2(v[c].z, v[c].w));
        uint2 u;
        u.x = *reinterpret_cast<uint32_t*>(&p0);
        u.y = *reinterpret_cast<uint32_t*>(&p1);
        dst[lane + 32 * c] = u;
    }
}

// ---------------- fused mma.sync GEMM + d2/min/label epilogue ----------------
// Grid (16, 128): x = 128-col tile, y = 128-row tile. 256 threads = 8 warps (2 M x 4 N).
// CTA tile 128x128, BK=64, cp.async double buffer, SW128 swizzle (128B rows).
// Warp tile 64x32 = 4x4 of m16n8k16; fp32 accumulate.
#define SMEM_A_OFF 0         // 2 x 16384
#define SMEM_B_OFF 32768     // 2 x 16384
#define SMEM_RM_OFF 65536    // 128 x 4B
#define SMEM_GEMM_TOTAL 66048

__global__ __launch_bounds__(256, 2)
void gemm_mma(const int* __restrict__ label) {
    extern __shared__ char smem[];
    const uint32_t smem_u32 = smem_to_u32(smem);
    const int tid  = threadIdx.x;
    const int lane = tid & 31;
    const int wid  = tid >> 5;
    const int warpM = wid >> 2;          // 0..1  -> rows warpM*64
    const int warpN = wid & 3;           // 0..3  -> cols warpN*32
    const int rowBase = blockIdx.y * 128;
    const int colBase = blockIdx.x * 128;

    unsigned* rowMinS = reinterpret_cast<unsigned*>(smem + SMEM_RM_OFF);
    if (tid < 128) rowMinS[tid] = 0x7F800000u;

    // tile loader: 128x64 bf16 (=128 rows x 128B) for A and B, 4+4 chunks/thread
    auto loadTile = [&](int kt, int s) {
        #pragma unroll
        for (int i = 0; i < 4; ++i) {
            int q = tid + 256 * i;           // 0..1023
            int row = q >> 3, kc = q & 7;
            const void* srcA = g_WO_bf + (size_t)(rowBase + row) * DIM + kt * 64 + kc * 8;
            CP_ASYNC_16(smem_u32 + SMEM_A_OFF + s * 16384 + SW128(row * 128 + kc * 16), srcA);
            const void* srcB = g_E_bf + (size_t)(colBase + row) * DIM + kt * 64 + kc * 8;
            CP_ASYNC_16(smem_u32 + SMEM_B_OFF + s * 16384 + SW128(row * 128 + kc * 16), srcB);
        }
        CP_ASYNC_COMMIT();
    };

    float acc[4][4][4];
    #pragma unroll
    for (int mt = 0; mt < 4; ++mt)
        #pragma unroll
        for (int nt = 0; nt < 4; ++nt)
            #pragma unroll
            for (int e = 0; e < 4; ++e) acc[mt][nt][e] = 0.f;

    // per-thread ldmatrix address components (byte offsets inside a tile)
    const int aRowOff = (warpM * 64 + (lane & 7) + ((lane >> 3) & 1) * 8) * 128 + (lane >> 4) * 16;
    const int bRowOff = (warpN * 32 + (lane & 7) + (lane >> 4) * 8) * 128 + ((lane >> 3) & 1) * 16;

    loadTile(0, 0);

    #pragma unroll 1
    for (int kt = 0; kt < 8; ++kt) {
        if (kt < 7) { loadTile(kt + 1, (kt + 1) & 1); CP_ASYNC_WAIT1(); }
        else        { CP_ASYNC_WAIT0(); }
        __syncthreads();
        const uint32_t sA = smem_u32 + SMEM_A_OFF + (kt & 1) * 16384;
        const uint32_t sB = smem_u32 + SMEM_B_OFF + (kt & 1) * 16384;
        #pragma unroll
        for (int ks = 0; ks < 4; ++ks) {
            uint32_t aF[4][4], bF[4][2];
            #pragma unroll
            for (int mt = 0; mt < 4; ++mt)
                ldsm_x4(aF[mt], sA + SW128(aRowOff + mt * 2048 + ks * 32));
            #pragma unroll
            for (int pr = 0; pr < 2; ++pr) {
                uint32_t t[4];
                ldsm_x4(t, sB + SW128(bRowOff + pr * 2048 + ks * 32));
                bF[2 * pr + 0][0] = t[0]; bF[2 * pr + 0][1] = t[1];
                bF[2 * pr + 1][0] = t[2]; bF[2 * pr + 1][1] = t[3];
            }
            #pragma unroll
            for (int mt = 0; mt < 4; ++mt)
                #pragma unroll
                for (int nt = 0; nt < 4; ++nt)
                    mma_16816(acc[mt][nt], aF[mt], bF[nt]);
        }
        __syncthreads();
    }

    // epilogue in d^2 space: d2 = x2 + e2 - 2*dot; exclude label col from min
    #pragma unroll
    for (int mt = 0; mt < 4; ++mt) {
        #pragma unroll
        for (int half = 0; half < 2; ++half) {
            int rl = warpM * 64 + mt * 16 + (lane >> 2) + half * 8;
            int r  = rowBase + rl;
            float x2v = __ldg(&d_x2[r]);
            int   lab = __ldg(&label[r]);
            float m = __int_as_float(0x7f800000);
            #pragma unroll
            for (int nt = 0; nt < 4; ++nt) {
                int c0 = colBase + warpN * 32 + nt * 8 + 2 * (lane & 3);
                float d20 = fmaf(-2.f, acc[mt][nt][half * 2 + 0], x2v + __ldg(&d_e2[c0]));
                float d21 = fmaf(-2.f, acc[mt][nt][half * 2 + 1], x2v + __ldg(&d_e2[c0 + 1]));
                if (c0 == lab)     d_labelD2[r] = d20;
                else               m = fminf(m, d20);
                if (c0 + 1 == lab) d_labelD2[r] = d21;
                else               m = fminf(m, d21);
            }
            m = fminf(m, __shfl_xor_sync(0xffffffffu, m, 1));
            m = fminf(m, __shfl_xor_sync(0xffffffffu, m, 2));
            if ((lane & 3) == 0) atomicMin(&rowMinS[rl], __float_as_uint(m));
        }
    }
    __syncthreads();
    if (tid < 128)
        atomicMin(&d_minBits[rowBase + tid], rowMinS[tid]);
}

// ---------------- final reduction: mean(margin + sqrt(labD2) - sqrt(minD2)) ----------------
__global__ void finalize(float* __restrict__ out) {
    __shared__ float sbuf[1024];
    int tid = threadIdx.x;
    float s = 0.f;
    for (int n = tid; n < N_ROWS; n += 1024) {
        float ld = sqrtf(fmaxf(d_labelD2[n], 0.f));
        float md = sqrtf(fmaxf(__uint_as_float(d_minBits[n]), 0.f));
        s += MARGIN + ld - md;
    }
    sbuf[tid] = s;
    __syncthreads();
    for (int off = 512; off > 0; off >>= 1) {
        if (tid < off) sbuf[tid] += sbuf[tid + off];
        __syncthreads();
    }
    if (tid == 0) out[0] = sbuf[0] / (float)N_ROWS;
}

// ---------------- launch ----------------
extern "C" void kernel_launch(void* const* d_in, const int* in_sizes, int n_in,
                              void* d_out, int out_size) {
    const float* WO    = (const float*)d_in[0];
    const float* E     = (const float*)d_in[1];
    const int*   label = (const int*)d_in[2];
    float* out = (float*)d_out;

    cudaFuncSetAttribute(gemm_mma, cudaFuncAttributeMaxDynamicSharedMemorySize, SMEM_GEMM_TOTAL);

    prep_wo<<<N_ROWS / 8, 256>>>(WO);
    prep_e<<<N_CLS / 8, 256>>>(E);
    dim3 grid(N_CLS / 128, N_ROWS / 128);   // (16, 128)
    gemm_mma<<<grid, 256, SMEM_GEMM_TOTAL>>>(label);
    finalize<<<1, 1024>>>(out);
}